// round 15
// baseline (speedup 1.0000x reference)
#include <cuda_runtime.h>
#include <cuda_bf16.h>
#include <cstdint>

// Problem constants
#define BB 2
#define SS 4096
#define DD 2048
#define HQ 32
#define HK 8
#define HH 32
#define DK 64
#define DV 64
#define OUT_D 2048
#define QKV 3072
#define NC 64
#define CH 64

// GEMM tiling: CTA 128x128, 4 warps (2x2), warp tile 64x64, BK=32, 3 stages,
// 2 CTAs/SM (R13/R14 champion).
#define BM 128
#define BN 128
#define BK 32
#define STAGES 3
#define SA_BYTES (BM * BK * 2)                  // 8192 per digit
#define SB_BYTES (BN * BK * 2)                  // 8192 per digit
#define STG_BYTES (2 * SA_BYTES + 2 * SB_BYTES) // 32768
#define MMA_SMEM (STAGES * STG_BYTES)           // 98304 per CTA

// ---------------- scratch (device globals; no allocation allowed) ----------
__device__ float g_proj[(size_t)BB * SS * QKV];
__device__ float g_kv[(size_t)BB * HK * NC * DK * DV];
__device__ float g_scum[(size_t)BB * HK * NC * DK * DV];
__device__ __align__(256) __nv_bfloat16 g_proj_hi[(size_t)BB * SS * QKV];
__device__ __align__(256) __nv_bfloat16 g_proj_lo[(size_t)BB * SS * QKV];
__device__ __align__(256) __nv_bfloat16 g_x_hi[(size_t)BB * SS * DD];
__device__ __align__(256) __nv_bfloat16 g_x_lo[(size_t)BB * SS * DD];
__device__ __align__(256) __nv_bfloat16 g_winT_hi[(size_t)QKV * DD];
__device__ __align__(256) __nv_bfloat16 g_winT_lo[(size_t)QKV * DD];
__device__ __align__(256) __nv_bfloat16 g_woutT_hi[(size_t)OUT_D * (HH * DV)];
__device__ __align__(256) __nv_bfloat16 g_woutT_lo[(size_t)OUT_D * (HH * DV)];
__device__ __align__(256) __nv_bfloat16 g_o_hi[(size_t)BB * SS * (HH * DV)];
__device__ __align__(256) __nv_bfloat16 g_o_lo[(size_t)BB * SS * (HH * DV)];

// ---------------------------------------------------------------------------
// PTX helpers (sm_80-level; valid on plain .target sm_103)
// ---------------------------------------------------------------------------
__device__ __forceinline__ uint32_t smem_u32(const void* p) {
    uint32_t a;
    asm("{ .reg .u64 t; cvta.to.shared.u64 t, %1; cvt.u32.u64 %0, t; }"
        : "=r"(a) : "l"(p));
    return a;
}
__device__ __forceinline__ void cp_async16(uint32_t dst, const void* src) {
    asm volatile("cp.async.cg.shared.global [%0], [%1], 16;"
                 :: "r"(dst), "l"(src) : "memory");
}
__device__ __forceinline__ void cp_commit() {
    asm volatile("cp.async.commit_group;" ::: "memory");
}
template <int N>
__device__ __forceinline__ void cp_wait() {
    asm volatile("cp.async.wait_group %0;" :: "n"(N) : "memory");
}
__device__ __forceinline__ void ldsm4(uint32_t* r, uint32_t addr) {
    asm volatile("ldmatrix.sync.aligned.m8n8.x4.shared.b16 {%0,%1,%2,%3}, [%4];"
                 : "=r"(r[0]), "=r"(r[1]), "=r"(r[2]), "=r"(r[3]) : "r"(addr));
}
__device__ __forceinline__ void ldsm4t(uint32_t* r, uint32_t addr) {
    asm volatile("ldmatrix.sync.aligned.m8n8.x4.trans.shared.b16 {%0,%1,%2,%3}, [%4];"
                 : "=r"(r[0]), "=r"(r[1]), "=r"(r[2]), "=r"(r[3]) : "r"(addr));
}
__device__ __forceinline__ void mma16816(float* d, const uint32_t* a,
                                         uint32_t b0, uint32_t b1) {
    asm volatile(
        "mma.sync.aligned.m16n8k16.row.col.f32.bf16.bf16.f32 "
        "{%0,%1,%2,%3}, {%4,%5,%6,%7}, {%8,%9}, {%0,%1,%2,%3};"
        : "+f"(d[0]), "+f"(d[1]), "+f"(d[2]), "+f"(d[3])
        : "r"(a[0]), "r"(a[1]), "r"(a[2]), "r"(a[3]), "r"(b0), "r"(b1));
}
__device__ __forceinline__ uint32_t swz(uint32_t off) {
    return off ^ (((off >> 7) & 7) << 4);
}

// ---------------------------------------------------------------------------
// split helpers
// ---------------------------------------------------------------------------
__device__ __forceinline__ void split2(float v, __nv_bfloat16& h, __nv_bfloat16& l) {
    h = __float2bfloat16(v);
    l = __float2bfloat16(v - __bfloat162float(h));
}
__device__ __forceinline__ uint32_t packbf2(__nv_bfloat16 a, __nv_bfloat16 b) {
    __nv_bfloat162 t = __halves2bfloat162(a, b);
    return *(uint32_t*)&t;
}
__device__ __forceinline__ void split4(float4 v, uint2& hi, uint2& lo) {
    __nv_bfloat16 h0, h1, h2, h3, l0, l1, l2, l3;
    split2(v.x, h0, l0); split2(v.y, h1, l1);
    split2(v.z, h2, l2); split2(v.w, h3, l3);
    hi.x = packbf2(h0, h1); hi.y = packbf2(h2, h3);
    lo.x = packbf2(l0, l1); lo.y = packbf2(l2, l3);
}

__global__ __launch_bounds__(256)
void convert_split(const float4* __restrict__ src, __nv_bfloat162* __restrict__ hi,
                   __nv_bfloat162* __restrict__ lo, int n4) {
    for (int i = blockIdx.x * 256 + threadIdx.x; i < n4; i += gridDim.x * 256) {
        float4 v = src[i];
        uint2 h, l;
        split4(v, h, l);
        ((uint32_t*)hi)[i * 2 + 0] = h.x;
        ((uint32_t*)hi)[i * 2 + 1] = h.y;
        ((uint32_t*)lo)[i * 2 + 0] = l.x;
        ((uint32_t*)lo)[i * 2 + 1] = l.y;
    }
}

// W[K][N] fp32 -> T_hi/T_lo [N][K] bf16 (tiled transpose)
__global__ __launch_bounds__(256)
void transpose_split(const float* __restrict__ W, __nv_bfloat16* __restrict__ Th,
                     __nv_bfloat16* __restrict__ Tl, int K, int N) {
    __shared__ float t[32][33];
    const int n0 = blockIdx.x * 32, k0 = blockIdx.y * 32;
    const int tx = threadIdx.x, ty = threadIdx.y;  // (32, 8)
    for (int i = ty; i < 32; i += 8)
        t[i][tx] = W[(size_t)(k0 + i) * N + n0 + tx];
    __syncthreads();
    for (int a = ty; a < 32; a += 8) {
        float v = t[tx][a];
        __nv_bfloat16 h, l;
        split2(v, h, l);
        Th[(size_t)(n0 + a) * K + k0 + tx] = h;
        Tl[(size_t)(n0 + a) * K + k0 + tx] = l;
    }
}

// ---------------------------------------------------------------------------
// Split-bf16 3-pass GEMM via mma.sync (R13 champion schedule).
// If Chi != nullptr, the epilogue also writes split hi/lo bf16 copies of C
// (same split2 of the same fp32 accumulators — bit-identical downstream).
// ---------------------------------------------------------------------------
__global__ __launch_bounds__(128, 2)
void gemm_mma(const __nv_bfloat16* __restrict__ Ah,
              const __nv_bfloat16* __restrict__ Al,
              const __nv_bfloat16* __restrict__ Bh,
              const __nv_bfloat16* __restrict__ Bl,
              float* __restrict__ C,
              __nv_bfloat16* __restrict__ Chi,
              __nv_bfloat16* __restrict__ Clo,
              int M, int N, int K) {
    extern __shared__ char smem[];
    const uint32_t sb = smem_u32(smem);
    const int tid = threadIdx.x;
    const int warp = tid >> 5, lane = tid & 31;
    const int wm = warp >> 1;
    const int wn = warp & 1;
    const int bm = blockIdx.y * BM;
    const int bn = blockIdx.x * BN;

    float acc[4][8][4];
#pragma unroll
    for (int i = 0; i < 4; i++)
#pragma unroll
        for (int j = 0; j < 8; j++)
#pragma unroll
            for (int k = 0; k < 4; k++) acc[i][j][k] = 0.f;

    const int arow0 = wm * 64 + (lane & 15);
    const int acol16 = ((lane >> 4) & 1);
    const int brow0 = wn * 64 + ((lane >> 4) & 1) * 8 + (lane & 7);
    const int bcol16 = ((lane >> 3) & 1);

    auto load_stage = [&](int t, int s) {
        const uint32_t base = sb + s * STG_BYTES;
        const int k0 = t * BK;
#pragma unroll
        for (int i = 0; i < 4; i++) {
            const int idx = tid + i * 128;
            const int r = idx >> 2, c = idx & 3;
            const uint32_t off = swz((uint32_t)(r * 64 + c * 16));
            const size_t ga = (size_t)(bm + r) * K + k0 + c * 8;
            const size_t gb = (size_t)(bn + r) * K + k0 + c * 8;
            cp_async16(base + off, Ah + ga);
            cp_async16(base + SA_BYTES + off, Al + ga);
            cp_async16(base + 2 * SA_BYTES + off, Bh + gb);
            cp_async16(base + 2 * SA_BYTES + SB_BYTES + off, Bl + gb);
        }
    };

#pragma unroll
    for (int s = 0; s < STAGES - 1; s++) { load_stage(s, s); cp_commit(); }

    const int nt = K / BK;
    int ls = STAGES - 1;
    int cs = 0;
    for (int t = 0; t < nt; t++) {
        cp_wait<STAGES - 2>();
        __syncthreads();
        if (t + STAGES - 1 < nt) {
            load_stage(t + STAGES - 1, ls);
            if (++ls == STAGES) ls = 0;
        }
        cp_commit();

        const uint32_t base = sb + cs * STG_BYTES;
        if (++cs == STAGES) cs = 0;
        const uint32_t ahB = base;
        const uint32_t alB = base + SA_BYTES;
        const uint32_t bhB = base + 2 * SA_BYTES;
        const uint32_t blB = bhB + SB_BYTES;

#pragma unroll
        for (int kk = 0; kk < 2; kk++) {
            uint32_t ahf[4][4], alf[4][4], bhf[4][4], blf[4][4];
#pragma unroll
            for (int mt = 0; mt < 4; mt++) {
                const uint32_t off = swz(
                    (uint32_t)((arow0 + mt * 16) * 64 + kk * 32 + acol16 * 16));
                ldsm4(ahf[mt], ahB + off);
                ldsm4(alf[mt], alB + off);
            }
#pragma unroll
            for (int n2 = 0; n2 < 4; n2++) {
                const uint32_t off = swz(
                    (uint32_t)((brow0 + n2 * 16) * 64 + kk * 32 + bcol16 * 16));
                ldsm4(bhf[n2], bhB + off);
                ldsm4(blf[n2], blB + off);
            }
#pragma unroll
            for (int mt = 0; mt < 4; mt++) {
#pragma unroll
                for (int n2 = 0; n2 < 4; n2++) {
                    mma16816(acc[mt][n2 * 2],     ahf[mt], bhf[n2][0], bhf[n2][1]);
                    mma16816(acc[mt][n2 * 2 + 1], ahf[mt], bhf[n2][2], bhf[n2][3]);
                    mma16816(acc[mt][n2 * 2],     ahf[mt], blf[n2][0], blf[n2][1]);
                    mma16816(acc[mt][n2 * 2 + 1], ahf[mt], blf[n2][2], blf[n2][3]);
                    mma16816(acc[mt][n2 * 2],     alf[mt], bhf[n2][0], bhf[n2][1]);
                    mma16816(acc[mt][n2 * 2 + 1], alf[mt], bhf[n2][2], bhf[n2][3]);
                }
            }
        }
    }

    // epilogue: fp32 C (+ optional split hi/lo copies)
#pragma unroll
    for (int mt = 0; mt < 4; mt++) {
        const int row = bm + wm * 64 + mt * 16 + (lane >> 2);
#pragma unroll
        for (int n8 = 0; n8 < 8; n8++) {
            const int col = bn + wn * 64 + n8 * 8 + ((lane & 3) << 1);
            const float a0 = acc[mt][n8][0], a1 = acc[mt][n8][1];
            const float a2 = acc[mt][n8][2], a3 = acc[mt][n8][3];
            *(float2*)&C[(size_t)row * N + col] = make_float2(a0, a1);
            *(float2*)&C[(size_t)(row + 8) * N + col] = make_float2(a2, a3);
            if (Chi) {
                __nv_bfloat16 h0, l0, h1, l1, h2, l2, h3, l3;
                split2(a0, h0, l0); split2(a1, h1, l1);
                split2(a2, h2, l2); split2(a3, h3, l3);
                *(uint32_t*)&Chi[(size_t)row * N + col] = packbf2(h0, h1);
                *(uint32_t*)&Clo[(size_t)row * N + col] = packbf2(l0, l1);
                *(uint32_t*)&Chi[(size_t)(row + 8) * N + col] = packbf2(h2, h3);
                *(uint32_t*)&Clo[(size_t)(row + 8) * N + col] = packbf2(l2, l3);
            }
        }
    }
}

// ---------------------------------------------------------------------------
// Phase A: per-chunk KV[b,hk,c][d][e] = sum_j k[j][d] * v[j][e]
// ---------------------------------------------------------------------------
__global__ __launch_bounds__(256)
void kv_kernel(const float* __restrict__ proj, float* __restrict__ kv) {
    const int c = blockIdx.x, hk = blockIdx.y, b = blockIdx.z;
    __shared__ float ks[64][64];
    __shared__ float vs[64][64];
    const int tid = threadIdx.x;

    const float* kb = proj + (size_t)(b * SS + c * CH) * QKV + HQ * DK + hk * DK;
    const float* vb = kb + HK * DK;

    for (int t = tid; t < 1024; t += 256) {
        const int r = t >> 4, c4 = (t & 15) << 2;
        *(float4*)&ks[r][c4] = *(const float4*)(kb + (size_t)r * QKV + c4);
        *(float4*)&vs[r][c4] = *(const float4*)(vb + (size_t)r * QKV + c4);
    }
    __syncthreads();

    const int tx = tid & 15, ty = tid >> 4;
    const int d0 = ty * 4, e0 = tx * 4;
    float acc[4][4];
#pragma unroll
    for (int i = 0; i < 4; i++)
#pragma unroll
        for (int j = 0; j < 4; j++) acc[i][j] = 0.f;

    for (int j = 0; j < 64; j++) {
        float kr[4], vr[4];
#pragma unroll
        for (int i = 0; i < 4; i++) kr[i] = ks[j][d0 + i];
#pragma unroll
        for (int e = 0; e < 4; e++) vr[e] = vs[j][e0 + e];
#pragma unroll
        for (int i = 0; i < 4; i++)
#pragma unroll
            for (int e = 0; e < 4; e++)
                acc[i][e] = fmaf(kr[i], vr[e], acc[i][e]);
    }

    float* dst = kv + ((size_t)((b * HK + hk) * NC + c)) * (DK * DV);
#pragma unroll
    for (int i = 0; i < 4; i++)
        *(float4*)(dst + (size_t)(d0 + i) * DV + e0) =
            make_float4(acc[i][0], acc[i][1], acc[i][2], acc[i][3]);
}

// ---------------------------------------------------------------------------
// Phase B: parallel exclusive prefix sum + fused final-state tail write.
// ---------------------------------------------------------------------------
__global__ __launch_bounds__(256)
void scan_kernel(const float* __restrict__ kv, float* __restrict__ scum,
                 const float* __restrict__ s0, float* __restrict__ out_tail) {
    const int bh = blockIdx.x;
    const int idx = blockIdx.y * 256 + threadIdx.x;   // 0..4095
    float run = 0.f;

    const size_t base = (size_t)bh * NC * (DK * DV) + idx;
#pragma unroll 4
    for (int c = 0; c < NC; c++) {
        const size_t off = base + (size_t)c * (DK * DV);
        scum[off] = run;
        run += kv[off];
    }
    const int b = bh >> 3, hkq = bh & 7;
#pragma unroll
    for (int hq = 0; hq < 4; hq++) {
        const size_t ob = (((size_t)(b * HH + hkq * 4 + hq)) << 12) + idx;
        out_tail[ob] = s0[ob] + run;
    }
}

// ---------------------------------------------------------------------------
// Phase C (tensor-core attn): per (chunk, head-pair, batch) block, 256 threads.
// q/k/v now loaded pre-split via cp.async from proj_hi/proj_lo; only the
// S = s0 + scum path does fp32 math.  Causal block-sparsity retained.
// ---------------------------------------------------------------------------
#define ATT_SMEM 81920
__global__ __launch_bounds__(256)
void attn_mma(const __nv_bfloat16* __restrict__ phi,
              const __nv_bfloat16* __restrict__ plo,
              const float* __restrict__ s0,
              const float* __restrict__ scum,
              __nv_bfloat16* __restrict__ o_hi,
              __nv_bfloat16* __restrict__ o_lo) {
    extern __shared__ char sm[];
    const uint32_t sb = smem_u32(sm);
    const uint32_t QH = 0, QL = 16384, SH = 32768, SL = 49152,
                   KB = 65536, KL2 = 73728;

    const int c = blockIdx.x, p = blockIdx.y, b = blockIdx.z;
    const int hk = p >> 1;
    const int tid = threadIdx.x, warp = tid >> 5, lane = tid & 31;

    const size_t rowbase = (size_t)(b * SS + c * CH) * QKV;
    const __nv_bfloat16* khi = phi + rowbase + HQ * DK + hk * DK;
    const __nv_bfloat16* klo = plo + rowbase + HQ * DK + hk * DK;
    const __nv_bfloat16* vhi = khi + HK * DK;
    const __nv_bfloat16* vlo = klo + HK * DK;
    const float* scb = scum + (size_t)((b * HK + hk) * NC + c) * (DK * DV);

    {
        const int lhq = tid >> 7;
        const int lh = p * 2 + lhq;
        const int wg = tid & 127;
        const uint32_t hoff = (uint32_t)lhq * 8192;
        const __nv_bfloat16* qhi = phi + rowbase + lh * DK;
        const __nv_bfloat16* qlo = plo + rowbase + lh * DK;
        // q: 512 16B transfers per digit per head -> 4 per wg-thread
#pragma unroll
        for (int i = 0; i < 4; i++) {
            const int idx = wg + i * 128;
            const int r = idx >> 3, cc = idx & 7;
            const uint32_t off = swz((uint32_t)(r * 128 + cc * 16));
            cp_async16(sb + QH + hoff + off, qhi + (size_t)r * QKV + cc * 8);
            cp_async16(sb + QL + hoff + off, qlo + (size_t)r * QKV + cc * 8);
        }
        // k (shared): 512 transfers per digit -> 2 per thread
#pragma unroll
        for (int i = 0; i < 2; i++) {
            const int idx = tid + i * 256;
            const int r = idx >> 3, cc = idx & 7;
            const uint32_t off = swz((uint32_t)(r * 128 + cc * 16));
            cp_async16(sb + KB + off, khi + (size_t)r * QKV + cc * 8);
            cp_async16(sb + KL2 + off, klo + (size_t)r * QKV + cc * 8);
        }
        cp_commit();

        // S = s0 + scum (fp32 path, per-head)
        const float* s0b = s0 + (size_t)(b * HH + lh) * (DK * DV);
        for (int t = wg; t < 1024; t += 128) {
            const int r = t >> 4, c4 = (t & 15) << 2;
            const uint32_t off = swz((uint32_t)(r * 128 + c4 * 2));
            float4 u = *(const float4*)(s0b + r * 64 + c4);
            float4 w = *(const float4*)(scb + r * 64 + c4);
            u.x += w.x; u.y += w.y; u.z += w.z; u.w += w.w;
            uint2 hi, lo;
            split4(u, hi, lo);
            *(uint2*)(sm + SH + hoff + off) = hi;
            *(uint2*)(sm + SL + hoff + off) = lo;
        }
        cp_wait<0>();
    }
    __syncthreads();

    const int hq = warp >> 2;
    const int wq = warp & 3;
    const int h = p * 2 + hq;
    const uint32_t hoff = (uint32_t)hq * 8192;
    const uint32_t qhB = sb + QH + hoff, qlB = sb + QL + hoff;
    const uint32_t shB = sb + SH + hoff, slB = sb + SL + hoff;
    const uint32_t kbB = sb + KB, klB = sb + KL2;

    float accO[8][4], accA[8][4];
#pragma unroll
    for (int i = 0; i < 8; i++)
#pragma unroll
        for (int j = 0; j < 4; j++) { accO[i][j] = 0.f; accA[i][j] = 0.f; }

    const int row0 = wq * 16;

#pragma unroll
    for (int kk = 0; kk < 4; kk++) {
        uint32_t qh[4], ql[4];
        const uint32_t aoff = swz(
            (uint32_t)((row0 + (lane & 15)) * 128 + kk * 32 + ((lane >> 4) & 1) * 16));
        ldsm4(qh, qhB + aoff);
        ldsm4(ql, qlB + aoff);
#pragma unroll
        for (int n2 = 0; n2 < 4; n2++) {
            uint32_t shf[4], slf[4];
            const uint32_t toff = swz(
                (uint32_t)((kk * 16 + (lane & 15)) * 128 +
                           (n2 * 16 + ((lane >> 4) & 1) * 8) * 2));
            ldsm4t(shf, shB + toff);
            ldsm4t(slf, slB + toff);

            mma16816(accO[n2 * 2],     qh, shf[0], shf[1]);
            mma16816(accO[n2 * 2 + 1], qh, shf[2], shf[3]);
            mma16816(accO[n2 * 2],     qh, slf[0], slf[1]);
            mma16816(accO[n2 * 2 + 1], qh, slf[2], slf[3]);
            mma16816(accO[n2 * 2],     ql, shf[0], shf[1]);
            mma16816(accO[n2 * 2 + 1], ql, shf[2], shf[3]);

            if (n2 <= wq) {
                uint32_t khf[4], klf[4];
                const uint32_t noff = swz(
                    (uint32_t)((n2 * 16 + ((lane >> 4) & 1) * 8 + (lane & 7)) * 128 +
                               kk * 32 + ((lane >> 3) & 1) * 16));
                ldsm4(khf, kbB + noff);
                ldsm4(klf, klB + noff);
                mma16816(accA[n2 * 2],     qh, khf[0], khf[1]);
                mma16816(accA[n2 * 2 + 1], qh, khf[2], khf[3]);
                mma16816(accA[n2 * 2],     qh, klf[0], klf[1]);
                mma16816(accA[n2 * 2 + 1], qh, klf[2], klf[3]);
                mma16816(accA[n2 * 2],     ql, khf[0], khf[1]);
                mma16816(accA[n2 * 2 + 1], ql, khf[2], khf[3]);
            }
        }
    }
    __syncthreads();   // all reads of S and k complete

    // mask + split-store A into this head's S buffers; load v (cp.async)
    const int rowa = row0 + (lane >> 2);
#pragma unroll
    for (int n8 = 0; n8 < 8; n8++) {
        const int colb = n8 * 8 + (lane & 3) * 2;
        const float a0 = (colb     <= rowa)     ? accA[n8][0] : 0.f;
        const float a1 = (colb + 1 <= rowa)     ? accA[n8][1] : 0.f;
        const float a2 = (colb     <= rowa + 8) ? accA[n8][2] : 0.f;
        const float a3 = (colb + 1 <= rowa + 8) ? accA[n8][3] : 0.f;
        __nv_bfloat16 h0, l0, h1, l1, h2, l2, h3, l3;
        split2(a0, h0, l0); split2(a1, h1, l1);
        split2(a2, h2, l2); split2(a3, h3, l3);
        const uint32_t o1 = swz((uint32_t)(rowa * 128 + colb * 2));
        const uint32_t o2 = swz((uint32_t)((rowa + 8) * 128 + colb * 2));
        *(uint32_t*)(sm + SH + hoff + o1) = packbf2(h0, h1);
        *(uint32_t*)(sm + SL + hoff + o1) = packbf2(l0, l1);
        *(uint32_t*)(sm + SH + hoff + o2) = packbf2(h2, h3);
        *(uint32_t*)(sm + SL + hoff + o2) = packbf2(l2, l3);
    }
#pragma unroll
    for (int i = 0; i < 2; i++) {
        const int idx = tid + i * 256;
        const int r = idx >> 3, cc = idx & 7;
        const uint32_t off = swz((uint32_t)(r * 128 + cc * 16));
        cp_async16(sb + KB + off, vhi + (size_t)r * QKV + cc * 8);
        cp_async16(sb + KL2 + off, vlo + (size_t)r * QKV + cc * 8);
    }
    cp_commit();
    cp_wait<0>();
    __syncthreads();

    // O += A @ v — causal: A row block has nonzero j only for kk <= wq
#pragma unroll
    for (int kk = 0; kk < 4; kk++) {
        if (kk > wq) break;
        uint32_t ahf[4], alf[4];
        const uint32_t aoff = swz(
            (uint32_t)((row0 + (lane & 15)) * 128 + kk * 32 + ((lane >> 4) & 1) * 16));
        ldsm4(ahf, shB + aoff);
        ldsm4(alf, slB + aoff);
#pragma unroll
        for (int n2 = 0; n2 < 4; n2++) {
            uint32_t vh[4], vl[4];
            const uint32_t toff = swz(
                (uint32_t)((kk * 16 + (lane & 15)) * 128 +
                           (n2 * 16 + ((lane >> 4) & 1) * 8) * 2));
            ldsm4t(vh, kbB + toff);
            ldsm4t(vl, klB + toff);
            mma16816(accO[n2 * 2],     ahf, vh[0], vh[1]);
            mma16816(accO[n2 * 2 + 1], ahf, vh[2], vh[3]);
            mma16816(accO[n2 * 2],     ahf, vl[0], vl[1]);
            mma16816(accO[n2 * 2 + 1], ahf, vl[2], vl[3]);
            mma16816(accO[n2 * 2],     alf, vh[0], vh[1]);
            mma16816(accO[n2 * 2 + 1], alf, vh[2], vh[3]);
        }
    }

    const size_t ob = (size_t)(b * SS + c * CH) * (HH * DV) + h * DV;
#pragma unroll
    for (int n8 = 0; n8 < 8; n8++) {
        const int colb = n8 * 8 + (lane & 3) * 2;
        __nv_bfloat16 h0, l0, h1, l1, h2, l2, h3, l3;
        split2(accO[n8][0], h0, l0); split2(accO[n8][1], h1, l1);
        split2(accO[n8][2], h2, l2); split2(accO[n8][3], h3, l3);
        const size_t r1 = ob + (size_t)rowa * (HH * DV) + colb;
        const size_t r2 = ob + (size_t)(rowa + 8) * (HH * DV) + colb;
        *(uint32_t*)(o_hi + r1) = packbf2(h0, h1);
        *(uint32_t*)(o_lo + r1) = packbf2(l0, l1);
        *(uint32_t*)(o_hi + r2) = packbf2(h2, h3);
        *(uint32_t*)(o_lo + r2) = packbf2(l2, l3);
    }
}

// ---------------------------------------------------------------------------
extern "C" void kernel_launch(void* const* d_in, const int* in_sizes, int n_in,
                              void* d_out, int out_size) {
    const float* x     = (const float*)d_in[0];   // [B,S,D]
    const float* s0    = (const float*)d_in[1];   // [B,H*DK*DV]
    const float* w_in  = (const float*)d_in[2];   // [D,QKV]
    const float* w_out = (const float*)d_in[3];   // [H*DV,OUT]
    float* out = (float*)d_out;

    float *proj, *kv, *scum;
    __nv_bfloat16 *proj_hi, *proj_lo;
    __nv_bfloat16 *x_hi, *x_lo, *winT_hi, *winT_lo, *woutT_hi, *woutT_lo, *o_hi, *o_lo;
    cudaGetSymbolAddress((void**)&proj, g_proj);
    cudaGetSymbolAddress((void**)&kv,   g_kv);
    cudaGetSymbolAddress((void**)&scum, g_scum);
    cudaGetSymbolAddress((void**)&proj_hi, g_proj_hi);
    cudaGetSymbolAddress((void**)&proj_lo, g_proj_lo);
    cudaGetSymbolAddress((void**)&x_hi, g_x_hi);
    cudaGetSymbolAddress((void**)&x_lo, g_x_lo);
    cudaGetSymbolAddress((void**)&winT_hi, g_winT_hi);
    cudaGetSymbolAddress((void**)&winT_lo, g_winT_lo);
    cudaGetSymbolAddress((void**)&woutT_hi, g_woutT_hi);
    cudaGetSymbolAddress((void**)&woutT_lo, g_woutT_lo);
    cudaGetSymbolAddress((void**)&o_hi, g_o_hi);
    cudaGetSymbolAddress((void**)&o_lo, g_o_lo);

    cudaFuncSetAttribute(gemm_mma,
                         cudaFuncAttributeMaxDynamicSharedMemorySize, MMA_SMEM);
    cudaFuncSetAttribute(attn_mma,
                         cudaFuncAttributeMaxDynamicSharedMemorySize, ATT_SMEM);

    const dim3 blk(256);

    // 0) input conversions
    convert_split<<<4096, blk>>>((const float4*)x, (__nv_bfloat162*)x_hi,
                                 (__nv_bfloat162*)x_lo, (BB * SS * DD) / 4);
    transpose_split<<<dim3(QKV / 32, DD / 32), dim3(32, 8)>>>(w_in, winT_hi, winT_lo,
                                                              DD, QKV);
    transpose_split<<<dim3(OUT_D / 32, (HH * DV) / 32), dim3(32, 8)>>>(
        w_out, woutT_hi, woutT_lo, HH * DV, OUT_D);

    // 1) proj = x @ W_in  (+ fused hi/lo split of proj)
    gemm_mma<<<dim3(QKV / BN, (BB * SS) / BM), dim3(128), MMA_SMEM>>>(
        x_hi, x_lo, winT_hi, winT_lo, proj, proj_hi, proj_lo, BB * SS, QKV, DD);

    // 2) per-chunk KV
    kv_kernel<<<dim3(NC, HK, BB), blk>>>(proj, kv);

    // 3) parallel exclusive prefix scan + fused final-state tail
    scan_kernel<<<dim3(BB * HK, 16), blk>>>(kv, scum, s0,
                                            out + (size_t)BB * SS * OUT_D);

    // 4) per-chunk outputs: pre-split q/k/v via cp.async
    attn_mma<<<dim3(NC, HH / 2, BB), blk, ATT_SMEM>>>(proj_hi, proj_lo, s0, scum,
                                                      o_hi, o_lo);

    // 5) out = o @ W_out  (no hi/lo)
    gemm_mma<<<dim3(OUT_D / BN, (BB * SS) / BM), dim3(128), MMA_SMEM>>>(
        o_hi, o_lo, woutT_hi, woutT_lo, out, nullptr, nullptr,
        BB * SS, OUT_D, HH * DV);
}

// round 16
// speedup vs baseline: 1.0095x; 1.0095x over previous
#include <cuda_runtime.h>
#include <cuda_bf16.h>
#include <cstdint>

// Problem constants
#define BB 2
#define SS 4096
#define DD 2048
#define HQ 32
#define HK 8
#define HH 32
#define DK 64
#define DV 64
#define OUT_D 2048
#define QKV 3072
#define NC 64
#define CH 64

// GEMM tiling: CTA 128x128, 4 warps (2x2), warp tile 64x64, BK=32, 3 stages,
// 2 CTAs/SM (R13/R14 champion schedule).
#define BM 128
#define BN 128
#define BK 32
#define STAGES 3
#define SA_BYTES (BM * BK * 2)                  // 8192 per digit
#define SB_BYTES (BN * BK * 2)                  // 8192 per digit
#define STG_BYTES (2 * SA_BYTES + 2 * SB_BYTES) // 32768
#define MMA_SMEM (STAGES * STG_BYTES)           // 98304 per CTA

// ---------------- scratch (device globals; no allocation allowed) ----------
__device__ float g_kv[(size_t)BB * HK * NC * DK * DV];
__device__ float g_scum[(size_t)BB * HK * NC * DK * DV];
__device__ __align__(256) __nv_bfloat16 g_proj_hi[(size_t)BB * SS * QKV];
__device__ __align__(256) __nv_bfloat16 g_proj_lo[(size_t)BB * SS * QKV];
__device__ __align__(256) __nv_bfloat16 g_x_hi[(size_t)BB * SS * DD];
__device__ __align__(256) __nv_bfloat16 g_x_lo[(size_t)BB * SS * DD];
__device__ __align__(256) __nv_bfloat16 g_winT_hi[(size_t)QKV * DD];
__device__ __align__(256) __nv_bfloat16 g_winT_lo[(size_t)QKV * DD];
__device__ __align__(256) __nv_bfloat16 g_woutT_hi[(size_t)OUT_D * (HH * DV)];
__device__ __align__(256) __nv_bfloat16 g_woutT_lo[(size_t)OUT_D * (HH * DV)];
__device__ __align__(256) __nv_bfloat16 g_o_hi[(size_t)BB * SS * (HH * DV)];
__device__ __align__(256) __nv_bfloat16 g_o_lo[(size_t)BB * SS * (HH * DV)];

// ---------------------------------------------------------------------------
// PTX helpers (sm_80-level; valid on plain .target sm_103)
// ---------------------------------------------------------------------------
__device__ __forceinline__ uint32_t smem_u32(const void* p) {
    uint32_t a;
    asm("{ .reg .u64 t; cvta.to.shared.u64 t, %1; cvt.u32.u64 %0, t; }"
        : "=r"(a) : "l"(p));
    return a;
}
__device__ __forceinline__ void cp_async16(uint32_t dst, const void* src) {
    asm volatile("cp.async.cg.shared.global [%0], [%1], 16;"
                 :: "r"(dst), "l"(src) : "memory");
}
__device__ __forceinline__ void cp_commit() {
    asm volatile("cp.async.commit_group;" ::: "memory");
}
template <int N>
__device__ __forceinline__ void cp_wait() {
    asm volatile("cp.async.wait_group %0;" :: "n"(N) : "memory");
}
__device__ __forceinline__ void ldsm4(uint32_t* r, uint32_t addr) {
    asm volatile("ldmatrix.sync.aligned.m8n8.x4.shared.b16 {%0,%1,%2,%3}, [%4];"
                 : "=r"(r[0]), "=r"(r[1]), "=r"(r[2]), "=r"(r[3]) : "r"(addr));
}
__device__ __forceinline__ void ldsm4t(uint32_t* r, uint32_t addr) {
    asm volatile("ldmatrix.sync.aligned.m8n8.x4.trans.shared.b16 {%0,%1,%2,%3}, [%4];"
                 : "=r"(r[0]), "=r"(r[1]), "=r"(r[2]), "=r"(r[3]) : "r"(addr));
}
__device__ __forceinline__ void mma16816(float* d, const uint32_t* a,
                                         uint32_t b0, uint32_t b1) {
    asm volatile(
        "mma.sync.aligned.m16n8k16.row.col.f32.bf16.bf16.f32 "
        "{%0,%1,%2,%3}, {%4,%5,%6,%7}, {%8,%9}, {%0,%1,%2,%3};"
        : "+f"(d[0]), "+f"(d[1]), "+f"(d[2]), "+f"(d[3])
        : "r"(a[0]), "r"(a[1]), "r"(a[2]), "r"(a[3]), "r"(b0), "r"(b1));
}
__device__ __forceinline__ uint32_t swz(uint32_t off) {
    return off ^ (((off >> 7) & 7) << 4);
}

// ---------------------------------------------------------------------------
// split helpers
// ---------------------------------------------------------------------------
__device__ __forceinline__ void split2(float v, __nv_bfloat16& h, __nv_bfloat16& l) {
    h = __float2bfloat16(v);
    l = __float2bfloat16(v - __bfloat162float(h));
}
__device__ __forceinline__ uint32_t packbf2(__nv_bfloat16 a, __nv_bfloat16 b) {
    __nv_bfloat162 t = __halves2bfloat162(a, b);
    return *(uint32_t*)&t;
}
__device__ __forceinline__ void split4(float4 v, uint2& hi, uint2& lo) {
    __nv_bfloat16 h0, h1, h2, h3, l0, l1, l2, l3;
    split2(v.x, h0, l0); split2(v.y, h1, l1);
    split2(v.z, h2, l2); split2(v.w, h3, l3);
    hi.x = packbf2(h0, h1); hi.y = packbf2(h2, h3);
    lo.x = packbf2(l0, l1); lo.y = packbf2(l2, l3);
}
// reconstruct 4 fp32 values from hi/lo bf16x2 pairs
__device__ __forceinline__ float4 join4(uint2 hi, uint2 lo) {
    float2 a = __bfloat1622float2(*(__nv_bfloat162*)&hi.x);
    float2 b = __bfloat1622float2(*(__nv_bfloat162*)&hi.y);
    float2 c = __bfloat1622float2(*(__nv_bfloat162*)&lo.x);
    float2 d = __bfloat1622float2(*(__nv_bfloat162*)&lo.y);
    return make_float4(a.x + c.x, a.y + c.y, b.x + d.x, b.y + d.y);
}

__global__ __launch_bounds__(256)
void convert_split(const float4* __restrict__ src, __nv_bfloat162* __restrict__ hi,
                   __nv_bfloat162* __restrict__ lo, int n4) {
    for (int i = blockIdx.x * 256 + threadIdx.x; i < n4; i += gridDim.x * 256) {
        float4 v = src[i];
        uint2 h, l;
        split4(v, h, l);
        ((uint32_t*)hi)[i * 2 + 0] = h.x;
        ((uint32_t*)hi)[i * 2 + 1] = h.y;
        ((uint32_t*)lo)[i * 2 + 0] = l.x;
        ((uint32_t*)lo)[i * 2 + 1] = l.y;
    }
}

// W[K][N] fp32 -> T_hi/T_lo [N][K] bf16 (tiled transpose)
__global__ __launch_bounds__(256)
void transpose_split(const float* __restrict__ W, __nv_bfloat16* __restrict__ Th,
                     __nv_bfloat16* __restrict__ Tl, int K, int N) {
    __shared__ float t[32][33];
    const int n0 = blockIdx.x * 32, k0 = blockIdx.y * 32;
    const int tx = threadIdx.x, ty = threadIdx.y;  // (32, 8)
    for (int i = ty; i < 32; i += 8)
        t[i][tx] = W[(size_t)(k0 + i) * N + n0 + tx];
    __syncthreads();
    for (int a = ty; a < 32; a += 8) {
        float v = t[tx][a];
        __nv_bfloat16 h, l;
        split2(v, h, l);
        Th[(size_t)(n0 + a) * K + k0 + tx] = h;
        Tl[(size_t)(n0 + a) * K + k0 + tx] = l;
    }
}

// ---------------------------------------------------------------------------
// Split-bf16 3-pass GEMM via mma.sync (R13 schedule).
// Writes EITHER fp32 C (Chi==null) OR split hi/lo bf16 (C==null) — never both.
// ---------------------------------------------------------------------------
__global__ __launch_bounds__(128, 2)
void gemm_mma(const __nv_bfloat16* __restrict__ Ah,
              const __nv_bfloat16* __restrict__ Al,
              const __nv_bfloat16* __restrict__ Bh,
              const __nv_bfloat16* __restrict__ Bl,
              float* __restrict__ C,
              __nv_bfloat16* __restrict__ Chi,
              __nv_bfloat16* __restrict__ Clo,
              int M, int N, int K) {
    extern __shared__ char smem[];
    const uint32_t sb = smem_u32(smem);
    const int tid = threadIdx.x;
    const int warp = tid >> 5, lane = tid & 31;
    const int wm = warp >> 1;
    const int wn = warp & 1;
    const int bm = blockIdx.y * BM;
    const int bn = blockIdx.x * BN;

    float acc[4][8][4];
#pragma unroll
    for (int i = 0; i < 4; i++)
#pragma unroll
        for (int j = 0; j < 8; j++)
#pragma unroll
            for (int k = 0; k < 4; k++) acc[i][j][k] = 0.f;

    const int arow0 = wm * 64 + (lane & 15);
    const int acol16 = ((lane >> 4) & 1);
    const int brow0 = wn * 64 + ((lane >> 4) & 1) * 8 + (lane & 7);
    const int bcol16 = ((lane >> 3) & 1);

    auto load_stage = [&](int t, int s) {
        const uint32_t base = sb + s * STG_BYTES;
        const int k0 = t * BK;
#pragma unroll
        for (int i = 0; i < 4; i++) {
            const int idx = tid + i * 128;
            const int r = idx >> 2, c = idx & 3;
            const uint32_t off = swz((uint32_t)(r * 64 + c * 16));
            const size_t ga = (size_t)(bm + r) * K + k0 + c * 8;
            const size_t gb = (size_t)(bn + r) * K + k0 + c * 8;
            cp_async16(base + off, Ah + ga);
            cp_async16(base + SA_BYTES + off, Al + ga);
            cp_async16(base + 2 * SA_BYTES + off, Bh + gb);
            cp_async16(base + 2 * SA_BYTES + SB_BYTES + off, Bl + gb);
        }
    };

#pragma unroll
    for (int s = 0; s < STAGES - 1; s++) { load_stage(s, s); cp_commit(); }

    const int nt = K / BK;
    int ls = STAGES - 1;
    int cs = 0;
    for (int t = 0; t < nt; t++) {
        cp_wait<STAGES - 2>();
        __syncthreads();
        if (t + STAGES - 1 < nt) {
            load_stage(t + STAGES - 1, ls);
            if (++ls == STAGES) ls = 0;
        }
        cp_commit();

        const uint32_t base = sb + cs * STG_BYTES;
        if (++cs == STAGES) cs = 0;
        const uint32_t ahB = base;
        const uint32_t alB = base + SA_BYTES;
        const uint32_t bhB = base + 2 * SA_BYTES;
        const uint32_t blB = bhB + SB_BYTES;

#pragma unroll
        for (int kk = 0; kk < 2; kk++) {
            uint32_t ahf[4][4], alf[4][4], bhf[4][4], blf[4][4];
#pragma unroll
            for (int mt = 0; mt < 4; mt++) {
                const uint32_t off = swz(
                    (uint32_t)((arow0 + mt * 16) * 64 + kk * 32 + acol16 * 16));
                ldsm4(ahf[mt], ahB + off);
                ldsm4(alf[mt], alB + off);
            }
#pragma unroll
            for (int n2 = 0; n2 < 4; n2++) {
                const uint32_t off = swz(
                    (uint32_t)((brow0 + n2 * 16) * 64 + kk * 32 + bcol16 * 16));
                ldsm4(bhf[n2], bhB + off);
                ldsm4(blf[n2], blB + off);
            }
#pragma unroll
            for (int mt = 0; mt < 4; mt++) {
#pragma unroll
                for (int n2 = 0; n2 < 4; n2++) {
                    mma16816(acc[mt][n2 * 2],     ahf[mt], bhf[n2][0], bhf[n2][1]);
                    mma16816(acc[mt][n2 * 2 + 1], ahf[mt], bhf[n2][2], bhf[n2][3]);
                    mma16816(acc[mt][n2 * 2],     ahf[mt], blf[n2][0], blf[n2][1]);
                    mma16816(acc[mt][n2 * 2 + 1], ahf[mt], blf[n2][2], blf[n2][3]);
                    mma16816(acc[mt][n2 * 2],     alf[mt], bhf[n2][0], bhf[n2][1]);
                    mma16816(acc[mt][n2 * 2 + 1], alf[mt], bhf[n2][2], bhf[n2][3]);
                }
            }
        }
    }

    // epilogue: EITHER fp32 OR split hi/lo (same byte volume as fp32)
    if (Chi) {
#pragma unroll
        for (int mt = 0; mt < 4; mt++) {
            const int row = bm + wm * 64 + mt * 16 + (lane >> 2);
#pragma unroll
            for (int n8 = 0; n8 < 8; n8++) {
                const int col = bn + wn * 64 + n8 * 8 + ((lane & 3) << 1);
                __nv_bfloat16 h0, l0, h1, l1, h2, l2, h3, l3;
                split2(acc[mt][n8][0], h0, l0); split2(acc[mt][n8][1], h1, l1);
                split2(acc[mt][n8][2], h2, l2); split2(acc[mt][n8][3], h3, l3);
                *(uint32_t*)&Chi[(size_t)row * N + col] = packbf2(h0, h1);
                *(uint32_t*)&Clo[(size_t)row * N + col] = packbf2(l0, l1);
                *(uint32_t*)&Chi[(size_t)(row + 8) * N + col] = packbf2(h2, h3);
                *(uint32_t*)&Clo[(size_t)(row + 8) * N + col] = packbf2(l2, l3);
            }
        }
    } else {
#pragma unroll
        for (int mt = 0; mt < 4; mt++) {
            const int row = bm + wm * 64 + mt * 16 + (lane >> 2);
#pragma unroll
            for (int n8 = 0; n8 < 8; n8++) {
                const int col = bn + wn * 64 + n8 * 8 + ((lane & 3) << 1);
                *(float2*)&C[(size_t)row * N + col] =
                    make_float2(acc[mt][n8][0], acc[mt][n8][1]);
                *(float2*)&C[(size_t)(row + 8) * N + col] =
                    make_float2(acc[mt][n8][2], acc[mt][n8][3]);
            }
        }
    }
}

// ---------------------------------------------------------------------------
// Phase A: per-chunk KV[b,hk,c][d][e] = sum_j k[j][d] * v[j][e]
// k, v reconstructed as hi+lo from the pre-split proj arrays.
// ---------------------------------------------------------------------------
__global__ __launch_bounds__(256)
void kv_kernel(const __nv_bfloat16* __restrict__ phi,
               const __nv_bfloat16* __restrict__ plo,
               float* __restrict__ kv) {
    const int c = blockIdx.x, hk = blockIdx.y, b = blockIdx.z;
    __shared__ float ks[64][64];
    __shared__ float vs[64][64];
    const int tid = threadIdx.x;

    const size_t rowbase = (size_t)(b * SS + c * CH) * QKV + HQ * DK + hk * DK;
    const __nv_bfloat16* khi = phi + rowbase;
    const __nv_bfloat16* klo = plo + rowbase;
    const __nv_bfloat16* vhi = khi + HK * DK;
    const __nv_bfloat16* vlo = klo + HK * DK;

    for (int t = tid; t < 1024; t += 256) {
        const int r = t >> 4, c4 = (t & 15) << 2;
        const size_t g = (size_t)r * QKV + c4;
        *(float4*)&ks[r][c4] = join4(*(const uint2*)(khi + g),
                                     *(const uint2*)(klo + g));
        *(float4*)&vs[r][c4] = join4(*(const uint2*)(vhi + g),
                                     *(const uint2*)(vlo + g));
    }
    __syncthreads();

    const int tx = tid & 15, ty = tid >> 4;
    const int d0 = ty * 4, e0 = tx * 4;
    float acc[4][4];
#pragma unroll
    for (int i = 0; i < 4; i++)
#pragma unroll
        for (int j = 0; j < 4; j++) acc[i][j] = 0.f;

    for (int j = 0; j < 64; j++) {
        float kr[4], vr[4];
#pragma unroll
        for (int i = 0; i < 4; i++) kr[i] = ks[j][d0 + i];
#pragma unroll
        for (int e = 0; e < 4; e++) vr[e] = vs[j][e0 + e];
#pragma unroll
        for (int i = 0; i < 4; i++)
#pragma unroll
            for (int e = 0; e < 4; e++)
                acc[i][e] = fmaf(kr[i], vr[e], acc[i][e]);
    }

    float* dst = kv + ((size_t)((b * HK + hk) * NC + c)) * (DK * DV);
#pragma unroll
    for (int i = 0; i < 4; i++)
        *(float4*)(dst + (size_t)(d0 + i) * DV + e0) =
            make_float4(acc[i][0], acc[i][1], acc[i][2], acc[i][3]);
}

// ---------------------------------------------------------------------------
// Phase B: parallel exclusive prefix sum + fused final-state tail write.
// ---------------------------------------------------------------------------
__global__ __launch_bounds__(256)
void scan_kernel(const float* __restrict__ kv, float* __restrict__ scum,
                 const float* __restrict__ s0, float* __restrict__ out_tail) {
    const int bh = blockIdx.x;
    const int idx = blockIdx.y * 256 + threadIdx.x;   // 0..4095
    float run = 0.f;

    const size_t base = (size_t)bh * NC * (DK * DV) + idx;
#pragma unroll 4
    for (int c = 0; c < NC; c++) {
        const size_t off = base + (size_t)c * (DK * DV);
        scum[off] = run;
        run += kv[off];
    }
    const int b = bh >> 3, hkq = bh & 7;
#pragma unroll
    for (int hq = 0; hq < 4; hq++) {
        const size_t ob = (((size_t)(b * HH + hkq * 4 + hq)) << 12) + idx;
        out_tail[ob] = s0[ob] + run;
    }
}

// ---------------------------------------------------------------------------
// Phase C (tensor-core attn): per (chunk, head-pair, batch) block, 256 threads.
// q/k/v loaded pre-split via cp.async; causal block-sparsity (R15 version).
// ---------------------------------------------------------------------------
#define ATT_SMEM 81920
__global__ __launch_bounds__(256)
void attn_mma(const __nv_bfloat16* __restrict__ phi,
              const __nv_bfloat16* __restrict__ plo,
              const float* __restrict__ s0,
              const float* __restrict__ scum,
              __nv_bfloat16* __restrict__ o_hi,
              __nv_bfloat16* __restrict__ o_lo) {
    extern __shared__ char sm[];
    const uint32_t sb = smem_u32(sm);
    const uint32_t QH = 0, QL = 16384, SH = 32768, SL = 49152,
                   KB = 65536, KL2 = 73728;

    const int c = blockIdx.x, p = blockIdx.y, b = blockIdx.z;
    const int hk = p >> 1;
    const int tid = threadIdx.x, warp = tid >> 5, lane = tid & 31;

    const size_t rowbase = (size_t)(b * SS + c * CH) * QKV;
    const __nv_bfloat16* khi = phi + rowbase + HQ * DK + hk * DK;
    const __nv_bfloat16* klo = plo + rowbase + HQ * DK + hk * DK;
    const __nv_bfloat16* vhi = khi + HK * DK;
    const __nv_bfloat16* vlo = klo + HK * DK;
    const float* scb = scum + (size_t)((b * HK + hk) * NC + c) * (DK * DV);

    {
        const int lhq = tid >> 7;
        const int lh = p * 2 + lhq;
        const int wg = tid & 127;
        const uint32_t hoff = (uint32_t)lhq * 8192;
        const __nv_bfloat16* qhi = phi + rowbase + lh * DK;
        const __nv_bfloat16* qlo = plo + rowbase + lh * DK;
#pragma unroll
        for (int i = 0; i < 4; i++) {
            const int idx = wg + i * 128;
            const int r = idx >> 3, cc = idx & 7;
            const uint32_t off = swz((uint32_t)(r * 128 + cc * 16));
            cp_async16(sb + QH + hoff + off, qhi + (size_t)r * QKV + cc * 8);
            cp_async16(sb + QL + hoff + off, qlo + (size_t)r * QKV + cc * 8);
        }
#pragma unroll
        for (int i = 0; i < 2; i++) {
            const int idx = tid + i * 256;
            const int r = idx >> 3, cc = idx & 7;
            const uint32_t off = swz((uint32_t)(r * 128 + cc * 16));
            cp_async16(sb + KB + off, khi + (size_t)r * QKV + cc * 8);
            cp_async16(sb + KL2 + off, klo + (size_t)r * QKV + cc * 8);
        }
        cp_commit();

        const float* s0b = s0 + (size_t)(b * HH + lh) * (DK * DV);
        for (int t = wg; t < 1024; t += 128) {
            const int r = t >> 4, c4 = (t & 15) << 2;
            const uint32_t off = swz((uint32_t)(r * 128 + c4 * 2));
            float4 u = *(const float4*)(s0b + r * 64 + c4);
            float4 w = *(const float4*)(scb + r * 64 + c4);
            u.x += w.x; u.y += w.y; u.z += w.z; u.w += w.w;
            uint2 hi, lo;
            split4(u, hi, lo);
            *(uint2*)(sm + SH + hoff + off) = hi;
            *(uint2*)(sm + SL + hoff + off) = lo;
        }
        cp_wait<0>();
    }
    __syncthreads();

    const int hq = warp >> 2;
    const int wq = warp & 3;
    const int h = p * 2 + hq;
    const uint32_t hoff = (uint32_t)hq * 8192;
    const uint32_t qhB = sb + QH + hoff, qlB = sb + QL + hoff;
    const uint32_t shB = sb + SH + hoff, slB = sb + SL + hoff;
    const uint32_t kbB = sb + KB, klB = sb + KL2;

    float accO[8][4], accA[8][4];
#pragma unroll
    for (int i = 0; i < 8; i++)
#pragma unroll
        for (int j = 0; j < 4; j++) { accO[i][j] = 0.f; accA[i][j] = 0.f; }

    const int row0 = wq * 16;

#pragma unroll
    for (int kk = 0; kk < 4; kk++) {
        uint32_t qh[4], ql[4];
        const uint32_t aoff = swz(
            (uint32_t)((row0 + (lane & 15)) * 128 + kk * 32 + ((lane >> 4) & 1) * 16));
        ldsm4(qh, qhB + aoff);
        ldsm4(ql, qlB + aoff);
#pragma unroll
        for (int n2 = 0; n2 < 4; n2++) {
            uint32_t shf[4], slf[4];
            const uint32_t toff = swz(
                (uint32_t)((kk * 16 + (lane & 15)) * 128 +
                           (n2 * 16 + ((lane >> 4) & 1) * 8) * 2));
            ldsm4t(shf, shB + toff);
            ldsm4t(slf, slB + toff);

            mma16816(accO[n2 * 2],     qh, shf[0], shf[1]);
            mma16816(accO[n2 * 2 + 1], qh, shf[2], shf[3]);
            mma16816(accO[n2 * 2],     qh, slf[0], slf[1]);
            mma16816(accO[n2 * 2 + 1], qh, slf[2], slf[3]);
            mma16816(accO[n2 * 2],     ql, shf[0], shf[1]);
            mma16816(accO[n2 * 2 + 1], ql, shf[2], shf[3]);

            if (n2 <= wq) {
                uint32_t khf[4], klf[4];
                const uint32_t noff = swz(
                    (uint32_t)((n2 * 16 + ((lane >> 4) & 1) * 8 + (lane & 7)) * 128 +
                               kk * 32 + ((lane >> 3) & 1) * 16));
                ldsm4(khf, kbB + noff);
                ldsm4(klf, klB + noff);
                mma16816(accA[n2 * 2],     qh, khf[0], khf[1]);
                mma16816(accA[n2 * 2 + 1], qh, khf[2], khf[3]);
                mma16816(accA[n2 * 2],     qh, klf[0], klf[1]);
                mma16816(accA[n2 * 2 + 1], qh, klf[2], klf[3]);
                mma16816(accA[n2 * 2],     ql, khf[0], khf[1]);
                mma16816(accA[n2 * 2 + 1], ql, khf[2], khf[3]);
            }
        }
    }
    __syncthreads();

    const int rowa = row0 + (lane >> 2);
#pragma unroll
    for (int n8 = 0; n8 < 8; n8++) {
        const int colb = n8 * 8 + (lane & 3) * 2;
        const float a0 = (colb     <= rowa)     ? accA[n8][0] : 0.f;
        const float a1 = (colb + 1 <= rowa)     ? accA[n8][1] : 0.f;
        const float a2 = (colb     <= rowa + 8) ? accA[n8][2] : 0.f;
        const float a3 = (colb + 1 <= rowa + 8) ? accA[n8][3] : 0.f;
        __nv_bfloat16 h0, l0, h1, l1, h2, l2, h3, l3;
        split2(a0, h0, l0); split2(a1, h1, l1);
        split2(a2, h2, l2); split2(a3, h3, l3);
        const uint32_t o1 = swz((uint32_t)(rowa * 128 + colb * 2));
        const uint32_t o2 = swz((uint32_t)((rowa + 8) * 128 + colb * 2));
        *(uint32_t*)(sm + SH + hoff + o1) = packbf2(h0, h1);
        *(uint32_t*)(sm + SL + hoff + o1) = packbf2(l0, l1);
        *(uint32_t*)(sm + SH + hoff + o2) = packbf2(h2, h3);
        *(uint32_t*)(sm + SL + hoff + o2) = packbf2(l2, l3);
    }
#pragma unroll
    for (int i = 0; i < 2; i++) {
        const int idx = tid + i * 256;
        const int r = idx >> 3, cc = idx & 7;
        const uint32_t off = swz((uint32_t)(r * 128 + cc * 16));
        cp_async16(sb + KB + off, vhi + (size_t)r * QKV + cc * 8);
        cp_async16(sb + KL2 + off, vlo + (size_t)r * QKV + cc * 8);
    }
    cp_commit();
    cp_wait<0>();
    __syncthreads();

#pragma unroll
    for (int kk = 0; kk < 4; kk++) {
        if (kk > wq) break;
        uint32_t ahf[4], alf[4];
        const uint32_t aoff = swz(
            (uint32_t)((row0 + (lane & 15)) * 128 + kk * 32 + ((lane >> 4) & 1) * 16));
        ldsm4(ahf, shB + aoff);
        ldsm4(alf, slB + aoff);
#pragma unroll
        for (int n2 = 0; n2 < 4; n2++) {
            uint32_t vh[4], vl[4];
            const uint32_t toff = swz(
                (uint32_t)((kk * 16 + (lane & 15)) * 128 +
                           (n2 * 16 + ((lane >> 4) & 1) * 8) * 2));
            ldsm4t(vh, kbB + toff);
            ldsm4t(vl, klB + toff);
            mma16816(accO[n2 * 2],     ahf, vh[0], vh[1]);
            mma16816(accO[n2 * 2 + 1], ahf, vh[2], vh[3]);
            mma16816(accO[n2 * 2],     ahf, vl[0], vl[1]);
            mma16816(accO[n2 * 2 + 1], ahf, vl[2], vl[3]);
            mma16816(accO[n2 * 2],     alf, vh[0], vh[1]);
            mma16816(accO[n2 * 2 + 1], alf, vh[2], vh[3]);
        }
    }

    const size_t ob = (size_t)(b * SS + c * CH) * (HH * DV) + h * DV;
#pragma unroll
    for (int n8 = 0; n8 < 8; n8++) {
        const int colb = n8 * 8 + (lane & 3) * 2;
        __nv_bfloat16 h0, l0, h1, l1, h2, l2, h3, l3;
        split2(accO[n8][0], h0, l0); split2(accO[n8][1], h1, l1);
        split2(accO[n8][2], h2, l2); split2(accO[n8][3], h3, l3);
        const size_t r1 = ob + (size_t)rowa * (HH * DV) + colb;
        const size_t r2 = ob + (size_t)(rowa + 8) * (HH * DV) + colb;
        *(uint32_t*)(o_hi + r1) = packbf2(h0, h1);
        *(uint32_t*)(o_lo + r1) = packbf2(l0, l1);
        *(uint32_t*)(o_hi + r2) = packbf2(h2, h3);
        *(uint32_t*)(o_lo + r2) = packbf2(l2, l3);
    }
}

// ---------------------------------------------------------------------------
extern "C" void kernel_launch(void* const* d_in, const int* in_sizes, int n_in,
                              void* d_out, int out_size) {
    const float* x     = (const float*)d_in[0];   // [B,S,D]
    const float* s0    = (const float*)d_in[1];   // [B,H*DK*DV]
    const float* w_in  = (const float*)d_in[2];   // [D,QKV]
    const float* w_out = (const float*)d_in[3];   // [H*DV,OUT]
    float* out = (float*)d_out;

    float *kv, *scum;
    __nv_bfloat16 *proj_hi, *proj_lo;
    __nv_bfloat16 *x_hi, *x_lo, *winT_hi, *winT_lo, *woutT_hi, *woutT_lo, *o_hi, *o_lo;
    cudaGetSymbolAddress((void**)&kv,   g_kv);
    cudaGetSymbolAddress((void**)&scum, g_scum);
    cudaGetSymbolAddress((void**)&proj_hi, g_proj_hi);
    cudaGetSymbolAddress((void**)&proj_lo, g_proj_lo);
    cudaGetSymbolAddress((void**)&x_hi, g_x_hi);
    cudaGetSymbolAddress((void**)&x_lo, g_x_lo);
    cudaGetSymbolAddress((void**)&winT_hi, g_winT_hi);
    cudaGetSymbolAddress((void**)&winT_lo, g_winT_lo);
    cudaGetSymbolAddress((void**)&woutT_hi, g_woutT_hi);
    cudaGetSymbolAddress((void**)&woutT_lo, g_woutT_lo);
    cudaGetSymbolAddress((void**)&o_hi, g_o_hi);
    cudaGetSymbolAddress((void**)&o_lo, g_o_lo);

    cudaFuncSetAttribute(gemm_mma,
                         cudaFuncAttributeMaxDynamicSharedMemorySize, MMA_SMEM);
    cudaFuncSetAttribute(attn_mma,
                         cudaFuncAttributeMaxDynamicSharedMemorySize, ATT_SMEM);

    const dim3 blk(256);

    // 0) input conversions
    convert_split<<<4096, blk>>>((const float4*)x, (__nv_bfloat162*)x_hi,
                                 (__nv_bfloat162*)x_lo, (BB * SS * DD) / 4);
    transpose_split<<<dim3(QKV / 32, DD / 32), dim3(32, 8)>>>(w_in, winT_hi, winT_lo,
                                                              DD, QKV);
    transpose_split<<<dim3(OUT_D / 32, (HH * DV) / 32), dim3(32, 8)>>>(
        w_out, woutT_hi, woutT_lo, HH * DV, OUT_D);

    // 1) proj = x @ W_in  -> split hi/lo ONLY (no fp32 proj)
    gemm_mma<<<dim3(QKV / BN, (BB * SS) / BM), dim3(128), MMA_SMEM>>>(
        x_hi, x_lo, winT_hi, winT_lo, nullptr, proj_hi, proj_lo, BB * SS, QKV, DD);

    // 2) per-chunk KV (k, v reconstructed as hi+lo)
    kv_kernel<<<dim3(NC, HK, BB), blk>>>(proj_hi, proj_lo, kv);

    // 3) parallel exclusive prefix scan + fused final-state tail
    scan_kernel<<<dim3(BB * HK, 16), blk>>>(kv, scum, s0,
                                            out + (size_t)BB * SS * OUT_D);

    // 4) per-chunk outputs: pre-split q/k/v via cp.async
    attn_mma<<<dim3(NC, HH / 2, BB), blk, ATT_SMEM>>>(proj_hi, proj_lo, s0, scum,
                                                      o_hi, o_lo);

    // 5) out = o @ W_out  (fp32 only)
    gemm_mma<<<dim3(OUT_D / BN, (BB * SS) / BM), dim3(128), MMA_SMEM>>>(
        o_hi, o_lo, woutT_hi, woutT_lo, out, nullptr, nullptr,
        BB * SS, OUT_D, HH * DV);
}